// round 8
// baseline (speedup 1.0000x reference)
#include <cuda_runtime.h>
#include <cuda_bf16.h>
#include <cstdint>

#define NN 100000
#define NE 300000
#define NEH 150000
#define MT 10000

typedef unsigned long long u64;
typedef unsigned int u32;
typedef __nv_bfloat16 bf16;

// ---------------- scratch (device globals; no allocation allowed) ----------------
__device__ float g_node_h [(size_t)NN*256];
__device__ float g_base   [(size_t)NE*256];
__device__ float g_y      [(size_t)NE*256];
__device__ float g_aggA   [(size_t)NN*256];
__device__ float g_aggB   [(size_t)NN*256];
__device__ float g_nodesum[(size_t)NN*256];
__device__ bf16 g_fn_h[(size_t)NN*256], g_fn_l[(size_t)NN*256];
__device__ bf16 g_fe_h[(size_t)NE*64],  g_fe_l[(size_t)NE*64];
__device__ bf16 g_tm_h[(size_t)MT*256], g_tm_l[(size_t)MT*256];
__device__ bf16 g_a_h [(size_t)NE*256], g_a_l [(size_t)NE*256];
__device__ bf16 g_ns_h[(size_t)NN*256], g_ns_l[(size_t)NN*256];
__device__ bf16 g_B1h[256*256], g_B1l[256*256];
__device__ bf16 g_B2h[256*64],  g_B2l[256*64];
__device__ bf16 g_B3h[256*256], g_B3l[256*256];
__device__ bf16 g_B4h[256*256], g_B4l[256*256];
__device__ bf16 g_B5h[256*256], g_B5l[256*256];

// ---------------- helpers ----------------
__device__ __forceinline__ u32 smem_u32(const void* p) {
    u32 a; asm("{ .reg .u64 t; cvta.to.shared.u64 t, %1; cvt.u32.u64 %0, t; }" : "=r"(a) : "l"(p));
    return a;
}
__device__ __forceinline__ void cp16(u32 dst, const void* src) {
    asm volatile("cp.async.cg.shared.global [%0], [%1], 16;" :: "r"(dst), "l"(src));
}
__device__ __forceinline__ void red2(float* p, float a, float b) {
    asm volatile("red.global.add.v2.f32 [%0], {%1,%2};" :: "l"(p), "f"(a), "f"(b) : "memory");
}
__device__ __forceinline__ void red4(float* p, float a, float b, float c, float d) {
    asm volatile("red.global.add.v4.f32 [%0], {%1,%2,%3,%4};"
                 :: "l"(p), "f"(a), "f"(b), "f"(c), "f"(d) : "memory");
}
__device__ __forceinline__ void ldsm4(u32* r, u32 addr) {
    asm volatile("ldmatrix.sync.aligned.m8n8.x4.shared.b16 {%0,%1,%2,%3}, [%4];"
                 : "=r"(r[0]), "=r"(r[1]), "=r"(r[2]), "=r"(r[3]) : "r"(addr));
}
__device__ __forceinline__ void mma16816(float* d, const u32* a, const u32* b) {
    asm volatile("mma.sync.aligned.m16n8k16.row.col.f32.bf16.bf16.f32 "
                 "{%0,%1,%2,%3}, {%4,%5,%6,%7}, {%8,%9}, {%0,%1,%2,%3};"
                 : "+f"(d[0]), "+f"(d[1]), "+f"(d[2]), "+f"(d[3])
                 : "r"(a[0]), "r"(a[1]), "r"(a[2]), "r"(a[3]), "r"(b[0]), "r"(b[1]));
}
__device__ __forceinline__ void split_store2(bf16* hp, bf16* lp, float x, float y) {
    bf16 hx = __float2bfloat16(x), hy = __float2bfloat16(y);
    __nv_bfloat162 h2; h2.x = hx; h2.y = hy;
    *(__nv_bfloat162*)hp = h2;
    __nv_bfloat162 l2;
    l2.x = __float2bfloat16(x - __bfloat162float(hx));
    l2.y = __float2bfloat16(y - __bfloat162float(hy));
    *(__nv_bfloat162*)lp = l2;
}
__device__ __forceinline__ void split_store4(bf16* hp, bf16* lp, float4 v) {
    split_store2(hp, lp, v.x, v.y);
    split_store2(hp + 2, lp + 2, v.z, v.w);
}

#define BUF_BYTES 10240u
#define STAGE_BYTES (4u * BUF_BYTES)
#define SM_BYTES (2 * STAGE_BYTES)       // 81920 -> 2 CTAs/SM

// ------------------- mma.sync GEMM: C[M,256] = A[M,K] @ W[K,256] -------------------
// MODE 0: C = acc
// MODE 1: C = acc + addmat[gidx[r]] + bias; also write relu-split to rh/rl
// MODE 2: C[gidx[r]] += acc; re-write relu-split of that row
// MODE 3: C = acc; red agg[gidx[r]] += acc
// MODE 4: C = acc + bias
// MODE 5: C = relu(C + acc)
template<int MODE>
__global__ __launch_bounds__(256, 2)
void tgemm(const bf16* __restrict__ Ah, const bf16* __restrict__ Al,
           const bf16* __restrict__ Bh, const bf16* __restrict__ Bl,
           float* __restrict__ C, int M, int K,
           const float* __restrict__ bias, const float* __restrict__ addmat,
           const int* __restrict__ gidx, float* __restrict__ agg,
           bf16* __restrict__ rh, bf16* __restrict__ rl)
{
    extern __shared__ char smem[];
    const u32 sb = smem_u32(smem);
    const int tid  = threadIdx.x;
    const int lane = tid & 31, w = tid >> 5;
    const int wm = w >> 2, wn = w & 3;
    const int bm = blockIdx.y * 128;
    const int bn = blockIdx.x * 128;
    const int nchunks = K >> 5;

    float acc[4][4][4];
    #pragma unroll
    for (int i = 0; i < 4; i++)
        #pragma unroll
        for (int j = 0; j < 4; j++)
            #pragma unroll
            for (int q = 0; q < 4; q++) acc[i][j][q] = 0.f;

    const int lr = tid >> 1;
    const int ch = (tid & 1) * 2;
    int growA = bm + lr; if (growA >= M) growA = M - 1;
    const u32 so = (u32)lr * 80u + (u32)ch * 16u;

    auto load_chunk = [&](int c, int s) {
        const u32 base = sb + (u32)s * STAGE_BYTES;
        const size_t gbA = ((size_t)growA * K + c * 32 + ch * 8) * 2;
        const size_t gbB = ((size_t)(bn + lr) * K + c * 32 + ch * 8) * 2;
        cp16(base + so,                  (const char*)Ah + gbA);
        cp16(base + so + 16,             (const char*)Ah + gbA + 16);
        cp16(base + BUF_BYTES + so,      (const char*)Al + gbA);
        cp16(base + BUF_BYTES + so + 16, (const char*)Al + gbA + 16);
        cp16(base + 2*BUF_BYTES + so,      (const char*)Bh + gbB);
        cp16(base + 2*BUF_BYTES + so + 16, (const char*)Bh + gbB + 16);
        cp16(base + 3*BUF_BYTES + so,      (const char*)Bl + gbB);
        cp16(base + 3*BUF_BYTES + so + 16, (const char*)Bl + gbB + 16);
    };

    const u32 aAddr = (u32)(wm * 64 + (lane & 15)) * 80u + (u32)(lane >> 4) * 16u;
    const u32 bAddr = (u32)(wn * 32 + ((lane >> 4) << 3) + (lane & 7)) * 80u
                    + (u32)((lane >> 3) & 1) * 16u;

    load_chunk(0, 0);
    asm volatile("cp.async.commit_group;" ::: "memory");

    for (int c = 0; c < nchunks; c++) {
        const int s = c & 1;
        if (c + 1 < nchunks) {
            load_chunk(c + 1, (c + 1) & 1);
            asm volatile("cp.async.commit_group;" ::: "memory");
            asm volatile("cp.async.wait_group 1;" ::: "memory");
        } else {
            asm volatile("cp.async.wait_group 0;" ::: "memory");
        }
        __syncthreads();

        const u32 stage = sb + (u32)s * STAGE_BYTES;
        #pragma unroll
        for (int t = 0; t < 3; t++) {
            const u32 sA = stage + ((t < 2) ? 0u : BUF_BYTES) + aAddr;
            const u32 sB = stage + ((t == 1) ? 3u : 2u) * BUF_BYTES + bAddr;
            #pragma unroll
            for (int ks = 0; ks < 2; ks++) {
                u32 af[4][4], bfv[2][4];
                #pragma unroll
                for (int mt = 0; mt < 4; mt++)
                    ldsm4(af[mt], sA + (u32)mt * (16u * 80u) + (u32)ks * 32u);
                #pragma unroll
                for (int p = 0; p < 2; p++)
                    ldsm4(bfv[p], sB + (u32)p * (16u * 80u) + (u32)ks * 32u);
                #pragma unroll
                for (int mt = 0; mt < 4; mt++)
                    #pragma unroll
                    for (int nt = 0; nt < 4; nt++)
                        mma16816(acc[mt][nt], af[mt], &bfv[nt >> 1][(nt & 1) * 2]);
            }
        }
        __syncthreads();
    }

    #pragma unroll
    for (int mt = 0; mt < 4; mt++) {
        #pragma unroll
        for (int half = 0; half < 2; half++) {
            const int r = bm + wm * 64 + mt * 16 + (lane >> 2) + half * 8;
            if (r >= M) continue;
            int g = 0;
            if (MODE == 1 || MODE == 2 || MODE == 3) g = __ldg(gidx + r);
            const size_t rowC = (size_t)r * 256;
            #pragma unroll
            for (int nt = 0; nt < 4; nt++) {
                const int c0 = bn + wn * 32 + nt * 8 + (lane & 3) * 2;
                float vx = acc[mt][nt][2 * half], vy = acc[mt][nt][2 * half + 1];
                if constexpr (MODE == 0) {
                    *(float2*)(C + rowC + c0) = make_float2(vx, vy);
                } else if constexpr (MODE == 1) {
                    const float2 ad = *(const float2*)(addmat + (size_t)g * 256 + c0);
                    const float2 bi = *(const float2*)(bias + c0);
                    vx += ad.x + bi.x; vy += ad.y + bi.y;
                    *(float2*)(C + rowC + c0) = make_float2(vx, vy);
                    split_store2(rh + rowC + c0, rl + rowC + c0,
                                 fmaxf(vx, 0.f), fmaxf(vy, 0.f));
                } else if constexpr (MODE == 2) {
                    const size_t rowG = (size_t)g * 256;
                    float2 bs = *(float2*)(C + rowG + c0);
                    bs.x += vx; bs.y += vy;
                    *(float2*)(C + rowG + c0) = bs;
                    split_store2(rh + rowG + c0, rl + rowG + c0,
                                 fmaxf(bs.x, 0.f), fmaxf(bs.y, 0.f));
                } else if constexpr (MODE == 3) {
                    *(float2*)(C + rowC + c0) = make_float2(vx, vy);
                    red2(agg + (size_t)g * 256 + c0, vx, vy);
                } else if constexpr (MODE == 4) {
                    const float2 bi = *(const float2*)(bias + c0);
                    *(float2*)(C + rowC + c0) = make_float2(vx + bi.x, vy + bi.y);
                } else if constexpr (MODE == 5) {
                    float2 o = *(float2*)(C + rowC + c0);
                    o.x = fmaxf(o.x + vx, 0.f); o.y = fmaxf(o.y + vy, 0.f);
                    *(float2*)(C + rowC + c0) = o;
                }
            }
        }
    }
}

// ---------------- prologue kernels (A on main stream, B on side stream) ----------------
#define PA_Z  (NN * 64)
#define PA_FN (NN * 64)
#define PA_W1 65536
#define PA_TOTAL (PA_Z + PA_FN + PA_W1)

__global__ __launch_bounds__(256)
void prologueA_k(const float* __restrict__ f_node, const float* __restrict__ W1)
{
    int i = blockIdx.x * blockDim.x + threadIdx.x;
    if (i >= PA_TOTAL) return;
    if (i < PA_Z) { ((float4*)g_aggA)[i] = make_float4(0.f,0.f,0.f,0.f); return; }
    i -= PA_Z;
    if (i < PA_FN) {
        float4 v = ((const float4*)f_node)[i];
        split_store4(g_fn_h + (size_t)i * 4, g_fn_l + (size_t)i * 4, v);
        return;
    }
    i -= PA_FN;
    int n = i >> 8, k = i & 255;
    float v = W1[(size_t)k * 256 + n];
    bf16 hi = __float2bfloat16(v);
    g_B1h[i] = hi;
    g_B1l[i] = __float2bfloat16(v - __bfloat162float(hi));
}

#define PB_Z  (2 * NN * 64)
#define PB_FE (NE * 16)
#define PB_TM (MT * 64)
#define PB_W  (16384 + 3 * 65536)
#define PB_TOTAL (PB_Z + PB_FE + PB_TM + PB_W)

__global__ __launch_bounds__(256)
void prologueB_k(const float* __restrict__ f_edge, const float* __restrict__ tree_msg,
                 const float* __restrict__ W2, const float* __restrict__ W3,
                 const float* __restrict__ W4, const float* __restrict__ W5)
{
    int i = blockIdx.x * blockDim.x + threadIdx.x;
    if (i >= PB_TOTAL) return;
    if (i < PB_Z) {
        if (i < NN * 64) ((float4*)g_aggB)[i] = make_float4(0.f,0.f,0.f,0.f);
        else ((float4*)g_nodesum)[i - NN * 64] = make_float4(0.f,0.f,0.f,0.f);
        return;
    }
    i -= PB_Z;
    if (i < PB_FE) {
        float4 v = ((const float4*)f_edge)[i];
        split_store4(g_fe_h + (size_t)i * 4, g_fe_l + (size_t)i * 4, v);
        return;
    }
    i -= PB_FE;
    if (i < PB_TM) {
        float4 v = ((const float4*)tree_msg)[i];
        split_store4(g_tm_h + (size_t)i * 4, g_tm_l + (size_t)i * 4, v);
        return;
    }
    i -= PB_TM;
    const float* W; bf16 *h, *l; int K;
    if (i < 16384)            { W = W2; h = g_B2h; l = g_B2l; K = 64; }
    else if (i < 16384 + 65536)   { i -= 16384; W = W3; h = g_B3h; l = g_B3l; K = 256; }
    else if (i < 16384 + 2*65536) { i -= 16384 + 65536; W = W4; h = g_B4h; l = g_B4l; K = 256; }
    else                      { i -= 16384 + 2*65536; W = W5; h = g_B5h; l = g_B5l; K = 256; }
    int n = i / K, k = i % K;
    float v = W[(size_t)k * 256 + n];
    bf16 hi = __float2bfloat16(v);
    h[i] = hi;
    l[i] = __float2bfloat16(v - __bfloat162float(hi));
}

// ---------------- combine: m = relu(base + agg[src] - y[e^1]) over nE edges --------
template<bool FINAL>
__global__ __launch_bounds__(256)
void combine_k(const float* __restrict__ base, const float* __restrict__ agg,
               const float* __restrict__ y, const int* __restrict__ esrc,
               const int* __restrict__ edst, int nE,
               bf16* __restrict__ mh, bf16* __restrict__ ml, float* __restrict__ nodesum)
{
    int gid = blockIdx.x * blockDim.x + threadIdx.x;
    if (gid >= nE * 32) return;
    int e = gid >> 5;
    int c = (gid & 31) << 3;
    int s = __ldg(esrc + e);
    const float* bp = base + (size_t)e * 256 + c;
    const float* ap = agg  + (size_t)s * 256 + c;
    const float* yp = y    + (size_t)(e ^ 1) * 256 + c;
    float4 b0 = ((const float4*)bp)[0], b1 = ((const float4*)bp)[1];
    float4 a0 = ((const float4*)ap)[0], a1 = ((const float4*)ap)[1];
    float4 y0 = ((const float4*)yp)[0], y1 = ((const float4*)yp)[1];
    float4 m0, m1;
    m0.x = fmaxf(b0.x + a0.x - y0.x, 0.f);
    m0.y = fmaxf(b0.y + a0.y - y0.y, 0.f);
    m0.z = fmaxf(b0.z + a0.z - y0.z, 0.f);
    m0.w = fmaxf(b0.w + a0.w - y0.w, 0.f);
    m1.x = fmaxf(b1.x + a1.x - y1.x, 0.f);
    m1.y = fmaxf(b1.y + a1.y - y1.y, 0.f);
    m1.z = fmaxf(b1.z + a1.z - y1.z, 0.f);
    m1.w = fmaxf(b1.w + a1.w - y1.w, 0.f);
    if (FINAL) {
        int d = __ldg(edst + e);
        float* np = nodesum + (size_t)d * 256 + c;
        red4(np,     m0.x, m0.y, m0.z, m0.w);
        red4(np + 4, m1.x, m1.y, m1.z, m1.w);
    } else {
        split_store4(mh + (size_t)e * 256 + c,     ml + (size_t)e * 256 + c,     m0);
        split_store4(mh + (size_t)e * 256 + c + 4, ml + (size_t)e * 256 + c + 4, m1);
    }
}

__global__ void split_k(const float* __restrict__ x, bf16* __restrict__ h,
                        bf16* __restrict__ l, int n4)
{
    int i = blockIdx.x * blockDim.x + threadIdx.x;
    if (i >= n4) return;
    float4 v = ((const float4*)x)[i];
    split_store4(h + (size_t)i * 4, l + (size_t)i * 4, v);
}

// --------------------------------- launch ---------------------------------
extern "C" void kernel_launch(void* const* d_in, const int* in_sizes, int n_in,
                              void* d_out, int out_size)
{
    const float* f_node   = (const float*)d_in[0];
    const float* f_edge   = (const float*)d_in[1];
    const float* tree_msg = (const float*)d_in[2];
    const float* W1       = (const float*)d_in[3];
    const float* W2       = (const float*)d_in[4];
    const float* W3       = (const float*)d_in[5];
    const float* b1       = (const float*)d_in[6];
    const float* W4       = (const float*)d_in[7];
    const float* W5       = (const float*)d_in[8];
    const float* b2       = (const float*)d_in[9];
    const int* edge_src   = (const int*)d_in[10];
    const int* edge_dst   = (const int*)d_in[11];
    const int* tree_tgt   = (const int*)d_in[12];
    float* out = (float*)d_out;

    float *node_h, *base, *y, *aggA, *aggB, *nodesum;
    bf16 *fnh, *fnl, *feh, *fel, *tmh, *tml, *ah, *al, *nsh, *nsl;
    bf16 *B1h, *B1l, *B2h, *B2l, *B3h, *B3l, *B4h, *B4l, *B5h, *B5l;
    cudaGetSymbolAddress((void**)&node_h,  g_node_h);
    cudaGetSymbolAddress((void**)&base,    g_base);
    cudaGetSymbolAddress((void**)&y,       g_y);
    cudaGetSymbolAddress((void**)&aggA,    g_aggA);
    cudaGetSymbolAddress((void**)&aggB,    g_aggB);
    cudaGetSymbolAddress((void**)&nodesum, g_nodesum);
    cudaGetSymbolAddress((void**)&fnh, g_fn_h); cudaGetSymbolAddress((void**)&fnl, g_fn_l);
    cudaGetSymbolAddress((void**)&feh, g_fe_h); cudaGetSymbolAddress((void**)&fel, g_fe_l);
    cudaGetSymbolAddress((void**)&tmh, g_tm_h); cudaGetSymbolAddress((void**)&tml, g_tm_l);
    cudaGetSymbolAddress((void**)&ah,  g_a_h);  cudaGetSymbolAddress((void**)&al,  g_a_l);
    cudaGetSymbolAddress((void**)&nsh, g_ns_h); cudaGetSymbolAddress((void**)&nsl, g_ns_l);
    cudaGetSymbolAddress((void**)&B1h, g_B1h);  cudaGetSymbolAddress((void**)&B1l, g_B1l);
    cudaGetSymbolAddress((void**)&B2h, g_B2h);  cudaGetSymbolAddress((void**)&B2l, g_B2l);
    cudaGetSymbolAddress((void**)&B3h, g_B3h);  cudaGetSymbolAddress((void**)&B3l, g_B3l);
    cudaGetSymbolAddress((void**)&B4h, g_B4h);  cudaGetSymbolAddress((void**)&B4l, g_B4l);
    cudaGetSymbolAddress((void**)&B5h, g_B5h);  cudaGetSymbolAddress((void**)&B5l, g_B5l);

    cudaFuncSetAttribute(tgemm<0>, cudaFuncAttributeMaxDynamicSharedMemorySize, SM_BYTES);
    cudaFuncSetAttribute(tgemm<1>, cudaFuncAttributeMaxDynamicSharedMemorySize, SM_BYTES);
    cudaFuncSetAttribute(tgemm<2>, cudaFuncAttributeMaxDynamicSharedMemorySize, SM_BYTES);
    cudaFuncSetAttribute(tgemm<3>, cudaFuncAttributeMaxDynamicSharedMemorySize, SM_BYTES);
    cudaFuncSetAttribute(tgemm<4>, cudaFuncAttributeMaxDynamicSharedMemorySize, SM_BYTES);
    cudaFuncSetAttribute(tgemm<5>, cudaFuncAttributeMaxDynamicSharedMemorySize, SM_BYTES);

    // one-time side stream + events (resource creation only; launched work is
    // identical and deterministic on every call)
    static cudaStream_t s2 = nullptr;
    static cudaEvent_t evFork, evPB, evCf1, evCf2, ev3b, ev4;
    if (!s2) {
        cudaStreamCreateWithFlags(&s2, cudaStreamNonBlocking);
        cudaEventCreateWithFlags(&evFork, cudaEventDisableTiming);
        cudaEventCreateWithFlags(&evPB,   cudaEventDisableTiming);
        cudaEventCreateWithFlags(&evCf1,  cudaEventDisableTiming);
        cudaEventCreateWithFlags(&evCf2,  cudaEventDisableTiming);
        cudaEventCreateWithFlags(&ev3b,   cudaEventDisableTiming);
        cudaEventCreateWithFlags(&ev4,    cudaEventDisableTiming);
    }

    const dim3 blk(256);
    const dim3 gN (2, (NN  + 127) / 128);
    const dim3 gE (2, (NE  + 127) / 128);
    const dim3 gEH(2, (NEH + 127) / 128);
    const dim3 gT (2, (MT  + 127) / 128);
    const int combH = (NEH * 32 + 255) / 256;
    const int combF = (NE  * 32 + 255) / 256;
    const size_t off = (size_t)NEH * 256;

    // fork side stream off the capture stream
    cudaEventRecord(evFork, 0);
    cudaStreamWaitEvent(s2, evFork, 0);

    // S1: prologueA (fn split, B1, zero aggA)  ||  S2: prologueB (rest)
    prologueA_k<<<(PA_TOTAL + 255) / 256, blk>>>(f_node, W1);
    prologueB_k<<<(PB_TOTAL + 255) / 256, blk, 0, s2>>>(f_edge, tree_msg, W2, W3, W4, W5);
    cudaEventRecord(evPB, s2);

    // S1: node_h = f_node @ W1 (overlaps prologueB)
    tgemm<0><<<gN, blk, SM_BYTES>>>(fnh, fnl, B1h, B1l, node_h, NN, 256,
                                    nullptr, nullptr, nullptr, nullptr, nullptr, nullptr);
    cudaStreamWaitEvent(0, evPB, 0);
    // S1: base = f_edge @ W2 + node_h[src] + b1 ; relu-split(ah/al)
    tgemm<1><<<gE, blk, SM_BYTES>>>(feh, fel, B2h, B2l, base, NE, 64,
                                    b1, node_h, edge_src, nullptr, ah, al);
    // S1: base[tree_tgt] += tree_msg @ W3 ; patch relu-split rows
    tgemm<2><<<gT, blk, SM_BYTES>>>(tmh, tml, B3h, B3l, base, MT, 256,
                                    nullptr, nullptr, tree_tgt, nullptr, ah, al);
    // S1: iter 1: y1 = relu(base) @ W3 ; aggA = segsum(y1, dst)
    tgemm<3><<<gE, blk, SM_BYTES>>>(ah, al, B3h, B3l, y, NE, 256,
                                    nullptr, nullptr, edge_dst, aggA, nullptr, nullptr);

    // S1: combineF(E1) -> cf1 ; combineF(E2) -> cf2
    combine_k<false><<<combH, blk>>>(base, aggA, y, edge_src, edge_dst, NEH, ah, al, nullptr);
    cudaEventRecord(evCf1, 0);
    combine_k<false><<<combH, blk>>>(base + off, aggA, y + off, edge_src + NEH,
                                     edge_dst + NEH, NEH, ah + off, al + off, nullptr);
    cudaEventRecord(evCf2, 0);

    // S2: iter 2 GEMM pipelined over edge halves; then independent readout gemm4
    cudaStreamWaitEvent(s2, evCf1, 0);
    tgemm<3><<<gEH, blk, SM_BYTES, s2>>>(ah, al, B3h, B3l, y, NEH, 256,
                                         nullptr, nullptr, edge_dst, aggB, nullptr, nullptr);
    cudaStreamWaitEvent(s2, evCf2, 0);
    tgemm<3><<<gEH, blk, SM_BYTES, s2>>>(ah + off, al + off, B3h, B3l, y + off, NEH, 256,
                                         nullptr, nullptr, edge_dst + NEH, aggB, nullptr, nullptr);
    cudaEventRecord(ev3b, s2);
    tgemm<4><<<gN, blk, SM_BYTES, s2>>>(fnh, fnl, B4h, B4l, out, NN, 256,
                                        b2, nullptr, nullptr, nullptr, nullptr, nullptr);
    cudaEventRecord(ev4, s2);

    // S1: iter 3 fused with readout reduce (overlaps gemm4 on S2)
    cudaStreamWaitEvent(0, ev3b, 0);
    combine_k<true><<<combF, blk>>>(base, aggB, y, edge_src, edge_dst, NE,
                                    nullptr, nullptr, nodesum);
    split_k<<<(NN * 64 + 255) / 256, blk>>>(nodesum, nsh, nsl, NN * 64);
    cudaStreamWaitEvent(0, ev4, 0);
    // S1: out = relu(out + node_sum @ W5)
    tgemm<5><<<gN, blk, SM_BYTES>>>(nsh, nsl, B5h, B5l, out, NN, 256,
                                    nullptr, nullptr, nullptr, nullptr, nullptr, nullptr);
}